// round 12
// baseline (speedup 1.0000x reference)
#include <cuda_runtime.h>
#include <cuda_fp16.h>
#include <math.h>

#define NN 50000
#define NE 800000
#define HEADS 8
#define HID 32
#define D1 (HEADS * HID)        // 256
#define D2 16
#define NEG_SLOPE 0.2f
#define FULL 0xffffffffu
#define CAP 64                  // max bucket slots (deg ~ Poisson(17))

#define NE4 (NE / 4)            // 200000
#define NN4 (NN / 4)            // 12500
#define SCAT_T (NE4 + NN4)      // 212500 scatter work items

#define NBLK 120                // <= SM count; guaranteed co-resident
#define NTHR 1024
#define NWARP (NBLK * 32)       // 3840 warps

#define LOG2E 1.4426950408889634f

// padded smem index: k + k/32 -> stride-8 access becomes conflict-free
#define PAD(k) ((k) + ((k) >> 5))

// ---------------- scratch (device globals; zero-initialized at load) ---------
__device__ int g_cursor[NN];                  // invariant: zero at launch entry
__device__ unsigned short g_bkt[NN * CAP];    // per-dst src lists (6.4 MB)

__device__ __align__(16) float4 g_x4[NN];           // packed node features
__device__ __align__(16) __half g_hmid_h[NN * D1];  // elu(layer1 out), fp16
__device__ __align__(16) __half g_h2h[NN * D2];     // layer2 features, fp16
__device__ float g_as2[NN];                          // pre-scaled by log2(e)
__device__ float g_ad2[NN];
__device__ unsigned g_bar[3];                        // grid barrier (monotonic)

__device__ __forceinline__ float lrelu(float x) {
    return x > 0.f ? x : NEG_SLOPE * x;
}
__device__ __forceinline__ float ex2(float x) {
    float r;
    asm("ex2.approx.f32 %0, %1;" : "=f"(r) : "f"(x));
    return r;
}
__device__ __forceinline__ void bput(int dst, int src) {
    int slot = atomicAdd(&g_cursor[dst], 1);
    if (slot < CAP) g_bkt[dst * CAP + slot] = (unsigned short)src;
}

// software grid barrier: monotonic counter, goal = next multiple of NBLK.
// Survives graph replays (never reset; unsigned wrap is ~4e9 arrivals away).
__device__ __forceinline__ void gridbar(int id) {
    __syncthreads();
    if (threadIdx.x == 0) {
        __threadfence();                       // publish this block's writes
        unsigned t = atomicAdd(&g_bar[id], 1) + 1;
        unsigned goal = ((t + NBLK - 1) / NBLK) * NBLK;
        while (*((volatile unsigned*)&g_bar[id]) < goal) __nanosleep(64);
    }
    __syncthreads();
}

// ---------------- the whole GAT encoder in one persistent kernel -------------
__global__ __launch_bounds__(NTHR, 1)
void k_all(const float* __restrict__ x,
           const int* __restrict__ ei,
           const float* __restrict__ W1,
           const float* __restrict__ atts1,
           const float* __restrict__ attd1,
           const float* __restrict__ bias1,
           const float* __restrict__ W2,
           const float* __restrict__ atts2,
           const float* __restrict__ attd2,
           const float* __restrict__ bias2,
           float* __restrict__ out) {
    __shared__ float W1s[PAD(767) + 1];
    __shared__ float b1s[PAD(255) + 1];
    __shared__ float W2s[D1 * D2];        // 16 KB
    __shared__ float As[24], Ad[24];      // folded att (x log2e)
    __shared__ float aS2[16], aD2[16];    // layer2 att (x log2e)

    int tid = threadIdx.x;
    int bid = blockIdx.x;

    // ---- load all weights into smem once per block ----
    for (int i = tid; i < 768; i += NTHR) W1s[PAD(i)] = W1[i];
    if (tid < 256) b1s[PAD(tid)] = bias1[tid];
    for (int i = tid; i < D1 * D2; i += NTHR) W2s[i] = W2[i];
    if (tid < 24) {
        int i = tid >> 3, h = tid & 7;
        float ss = 0.f, sd = 0.f;
        #pragma unroll
        for (int c = 0; c < HID; c++) {
            float w = __ldg(&W1[i * D1 + h * HID + c]);
            ss = fmaf(w, __ldg(&atts1[h * HID + c]), ss);
            sd = fmaf(w, __ldg(&attd1[h * HID + c]), sd);
        }
        As[tid] = ss * LOG2E;
        Ad[tid] = sd * LOG2E;
    }
    if (tid < 16) {
        aS2[tid] = atts2[tid] * LOG2E;
        aD2[tid] = attd2[tid] * LOG2E;
    }

    // ================= phase 1: bucket build + x packing =================
    for (int t = bid * NTHR + tid; t < SCAT_T; t += NBLK * NTHR) {
        if (t < NE4) {
            int4 S = __ldg(reinterpret_cast<const int4*>(ei) + t);
            int4 D = __ldg(reinterpret_cast<const int4*>(ei + NE) + t);
            bput(D.x, S.x);
            bput(D.y, S.y);
            bput(D.z, S.z);
            bput(D.w, S.w);
        } else {
            int m = t - NE4;
            int n0 = m * 4;
            const float4* xv = reinterpret_cast<const float4*>(x) + m * 3;
            float4 a = __ldg(xv), b = __ldg(xv + 1), c = __ldg(xv + 2);
            g_x4[n0 + 0] = make_float4(a.x, a.y, a.z, 0.f);
            g_x4[n0 + 1] = make_float4(a.w, b.x, b.y, 0.f);
            g_x4[n0 + 2] = make_float4(b.z, b.w, c.x, 0.f);
            g_x4[n0 + 3] = make_float4(c.y, c.z, c.w, 0.f);
            bput(n0 + 0, n0 + 0);
            bput(n0 + 1, n0 + 1);
            bput(n0 + 2, n0 + 2);
            bput(n0 + 3, n0 + 3);
        }
    }
    gridbar(0);

    // ======== phase 2: layer1 gather-softmax-agg-transform + ELU ========
    // one warp per node; 8 edge subgroups x 4 lanes; lane covers heads q, q+4
    {
        int lane = tid & 31;
        int q = lane & 3;
        int g = lane >> 2;
        float A00 = As[q],     A01 = As[8 + q],  A02 = As[16 + q];
        float A10 = As[4 + q], A11 = As[12 + q], A12 = As[20 + q];

        for (int n = bid * 32 + (tid >> 5); n < NN; n += NWARP) {
            int deg = min(g_cursor[n], CAP);
            const unsigned short* row = g_bkt + n * CAP;
            float4 xn = g_x4[n];
            float adh0 = fmaf(xn.x, Ad[q],     fmaf(xn.y, Ad[8 + q],  xn.z * Ad[16 + q]));
            float adh1 = fmaf(xn.x, Ad[4 + q], fmaf(xn.y, Ad[12 + q], xn.z * Ad[20 + q]));

            float sx0 = 0.f, sy0 = 0.f, sz0 = 0.f, sw0 = 0.f;
            float sx1 = 0.f, sy1 = 0.f, sz1 = 0.f, sw1 = 0.f;
            for (int j = g; j < deg; j += 8) {
                int s = (int)row[j];
                float4 xs = __ldg(&g_x4[s]);
                float as0 = fmaf(xs.x, A00, fmaf(xs.y, A01, xs.z * A02));
                float as1 = fmaf(xs.x, A10, fmaf(xs.y, A11, xs.z * A12));
                float w0 = ex2(lrelu(as0 + adh0));
                float w1 = ex2(lrelu(as1 + adh1));
                sw0 += w0;
                sx0 = fmaf(w0, xs.x, sx0); sy0 = fmaf(w0, xs.y, sy0); sz0 = fmaf(w0, xs.z, sz0);
                sw1 += w1;
                sx1 = fmaf(w1, xs.x, sx1); sy1 = fmaf(w1, xs.y, sy1); sz1 = fmaf(w1, xs.z, sz1);
            }
            #pragma unroll
            for (int off = 4; off <= 16; off <<= 1) {
                sx0 += __shfl_xor_sync(FULL, sx0, off);
                sy0 += __shfl_xor_sync(FULL, sy0, off);
                sz0 += __shfl_xor_sync(FULL, sz0, off);
                sw0 += __shfl_xor_sync(FULL, sw0, off);
                sx1 += __shfl_xor_sync(FULL, sx1, off);
                sy1 += __shfl_xor_sync(FULL, sy1, off);
                sz1 += __shfl_xor_sync(FULL, sz1, off);
                sw1 += __shfl_xor_sync(FULL, sw1, off);
            }
            int hc = lane >> 2;
            int srcl = hc & 3;
            float tx0 = __shfl_sync(FULL, sx0, srcl), tx1 = __shfl_sync(FULL, sx1, srcl);
            float ty0 = __shfl_sync(FULL, sy0, srcl), ty1 = __shfl_sync(FULL, sy1, srcl);
            float tz0 = __shfl_sync(FULL, sz0, srcl), tz1 = __shfl_sync(FULL, sz1, srcl);
            float tw0 = __shfl_sync(FULL, sw0, srcl), tw1 = __shfl_sync(FULL, sw1, srcl);
            bool lo = hc < 4;
            float ex = lo ? tx0 : tx1;
            float ey = lo ? ty0 : ty1;
            float ez = lo ? tz0 : tz1;
            float ew = lo ? tw0 : tw1;
            float inv = 1.0f / (ew + 1e-16f);
            ex *= inv; ey *= inv; ez *= inv;

            int c0 = lane * 8;
            float o[8];
            #pragma unroll
            for (int i = 0; i < 8; i++) {
                int k = c0 + i;
                float v = fmaf(ex, W1s[PAD(k)],
                          fmaf(ey, W1s[PAD(256 + k)], ez * W1s[PAD(512 + k)]));
                v += b1s[PAD(k)];
                o[i] = v > 0.f ? v : (ex2(v * LOG2E) - 1.0f);   // ELU
            }
            __half2 p0 = __floats2half2_rn(o[0], o[1]);
            __half2 p1 = __floats2half2_rn(o[2], o[3]);
            __half2 p2 = __floats2half2_rn(o[4], o[5]);
            __half2 p3 = __floats2half2_rn(o[6], o[7]);
            uint4 pack;
            pack.x = *reinterpret_cast<unsigned int*>(&p0);
            pack.y = *reinterpret_cast<unsigned int*>(&p1);
            pack.z = *reinterpret_cast<unsigned int*>(&p2);
            pack.w = *reinterpret_cast<unsigned int*>(&p3);
            reinterpret_cast<uint4*>(g_hmid_h)[n * 32 + lane] = pack;
        }
    }
    gridbar(1);

    // ============ phase 3: layer2 node transform (256 -> 16) ============
    {
        int grp = tid >> 4;     // 64 nodes per block iteration
        int c   = tid & 15;
        for (int base = bid * 64; base < NN; base += NBLK * 64) {
            int n = base + grp;
            if (n < NN) {
                const uint4* row = reinterpret_cast<const uint4*>(g_hmid_h + n * D1);
                float acc = 0.f;
                #pragma unroll 8
                for (int qq = 0; qq < 32; qq++) {
                    uint4 v = row[qq];
                    int k = qq * 8;
                    const __half2* p = reinterpret_cast<const __half2*>(&v);
                    #pragma unroll
                    for (int t = 0; t < 4; t++) {
                        float2 f = __half22float2(p[t]);
                        acc = fmaf(f.x, W2s[(k + 2 * t) * D2 + c], acc);
                        acc = fmaf(f.y, W2s[(k + 2 * t + 1) * D2 + c], acc);
                    }
                }
                g_h2h[n * D2 + c] = __float2half_rn(acc);
                float sa = acc * aS2[c];     // pre-scaled by log2e
                float sd = acc * aD2[c];
                #pragma unroll
                for (int off = 8; off > 0; off >>= 1) {
                    sa += __shfl_xor_sync(FULL, sa, off, 16);
                    sd += __shfl_xor_sync(FULL, sd, off, 16);
                }
                if (c == 0) { g_as2[n] = sa; g_ad2[n] = sd; }
            }
        }
    }
    gridbar(2);

    // ============ phase 4: layer2 softmax-agg + bias + cursor reset ======
    {
        int lane = tid & 31;
        int q = lane & 3;       // channel quad owner
        int g = lane >> 2;      // edge subgroup 0..7
        for (int n = bid * 32 + (tid >> 5); n < NN; n += NWARP) {
            int deg = min(g_cursor[n], CAP);
            const unsigned short* row = g_bkt + n * CAP;
            float adn = g_ad2[n];

            float a0 = 0.f, a1 = 0.f, a2 = 0.f, a3 = 0.f, wsum = 0.f;
            for (int j = g; j < deg; j += 8) {
                int s = (int)row[j];
                float w = ex2(lrelu(g_as2[s] + adn));
                uint2 v = *reinterpret_cast<const uint2*>(g_h2h + s * D2 + q * 4);
                float2 f0 = __half22float2(*reinterpret_cast<__half2*>(&v.x));
                float2 f1 = __half22float2(*reinterpret_cast<__half2*>(&v.y));
                a0 = fmaf(w, f0.x, a0);
                a1 = fmaf(w, f0.y, a1);
                a2 = fmaf(w, f1.x, a2);
                a3 = fmaf(w, f1.y, a3);
                wsum += w;
            }
            #pragma unroll
            for (int off = 4; off <= 16; off <<= 1) {
                a0   += __shfl_xor_sync(FULL, a0, off);
                a1   += __shfl_xor_sync(FULL, a1, off);
                a2   += __shfl_xor_sync(FULL, a2, off);
                a3   += __shfl_xor_sync(FULL, a3, off);
                wsum += __shfl_xor_sync(FULL, wsum, off);
            }
            if (lane < 4) {
                float inv = 1.0f / (wsum + 1e-16f);
                int c = q * 4;
                float4 r;
                r.x = a0 * inv + bias2[c];
                r.y = a1 * inv + bias2[c + 1];
                r.z = a2 * inv + bias2[c + 2];
                r.w = a3 * inv + bias2[c + 3];
                *reinterpret_cast<float4*>(out + n * D2 + c) = r;
            }
            if (lane == 0) g_cursor[n] = 0;   // restore zero invariant
        }
    }
}

// ---------------- launch ------------------------------------------------------
extern "C" void kernel_launch(void* const* d_in, const int* in_sizes, int n_in,
                              void* d_out, int out_size) {
    const float* x      = (const float*)d_in[0];
    const int*   ei     = (const int*)d_in[1];   // JAX x64 disabled -> int32
    const float* W1     = (const float*)d_in[2];
    const float* atts1  = (const float*)d_in[3];
    const float* attd1  = (const float*)d_in[4];
    const float* bias1  = (const float*)d_in[5];
    const float* W2     = (const float*)d_in[6];
    const float* atts2  = (const float*)d_in[7];
    const float* attd2  = (const float*)d_in[8];
    const float* bias2  = (const float*)d_in[9];
    float* out = (float*)d_out;

    k_all<<<NBLK, NTHR>>>(x, ei, W1, atts1, attd1, bias1,
                          W2, atts2, attd2, bias2, out);
}

// round 14
// speedup vs baseline: 1.2314x; 1.2314x over previous
#include <cuda_runtime.h>
#include <cuda_fp16.h>
#include <math.h>

#define NN 50000
#define NE 800000
#define HEADS 8
#define HID 32
#define D1 (HEADS * HID)        // 256
#define D2 16
#define NEG_SLOPE 0.2f
#define FULL 0xffffffffu
#define CAP 64                  // max bucket slots (deg ~ Poisson(17); P(>64)~1e-19)

#define NE8 (NE / 8)            // 100000 edge work items (8 edges each)
#define NN4 (NN / 4)            // 12500 node work items (4 nodes each)
#define SCAT_T (NE8 + NN4)      // 112500 scatter threads

// padded smem index: k + k/32 -> stride-8 access becomes conflict-free
#define PAD(k) ((k) + ((k) >> 5))

// ---------------- scratch (device globals; zero-initialized at load) ---------
__device__ int g_cursor[NN];                  // invariant: zero at launch entry
__device__ unsigned short g_bkt[NN * CAP];    // per-dst src lists (6.4 MB)

__device__ __align__(16) float4 g_x4[NN];           // packed node features
__device__ __align__(16) __half g_hmid_h[NN * D1];  // elu(layer1 out), fp16
__device__ __align__(16) __half g_h2h[NN * D2];     // layer2 features, fp16
__device__ float g_as2[NN];
__device__ float g_ad2[NN];
__device__ float g_As1[24];   // [i*8+h]: att_src folded through W1 (3x8)
__device__ float g_Ad1[24];

__device__ __forceinline__ float lrelu(float x) {
    return x > 0.f ? x : NEG_SLOPE * x;
}
__device__ __forceinline__ void bput(int dst, int src) {
    int slot = atomicAdd(&g_cursor[dst], 1);
    if (slot < CAP) g_bkt[dst * CAP + slot] = (unsigned short)src;
}

// ---------------- bucket build (8 edges/thread) + x packing + att prep -------
__global__ void k_scatter(const int* __restrict__ ei,
                          const float* __restrict__ x,
                          const float* __restrict__ W1,
                          const float* __restrict__ atts1,
                          const float* __restrict__ attd1) {
    if (blockIdx.x == gridDim.x - 1) {
        int t = threadIdx.x;
        if (t < 24) {
            int i = t >> 3, h = t & 7;
            float ss = 0.f, sd = 0.f;
            #pragma unroll
            for (int c = 0; c < HID; c++) {
                float w = __ldg(&W1[i * D1 + h * HID + c]);
                ss = fmaf(w, __ldg(&atts1[h * HID + c]), ss);
                sd = fmaf(w, __ldg(&attd1[h * HID + c]), sd);
            }
            g_As1[i * 8 + h] = ss;
            g_Ad1[i * 8 + h] = sd;
        }
        return;
    }
    int t = blockIdx.x * 256 + threadIdx.x;
    if (t < NE8) {
        const int4* s4 = reinterpret_cast<const int4*>(ei);
        const int4* d4 = reinterpret_cast<const int4*>(ei + NE);
        int4 Sa = __ldg(s4 + 2 * t), Sb = __ldg(s4 + 2 * t + 1);
        int4 Da = __ldg(d4 + 2 * t), Db = __ldg(d4 + 2 * t + 1);
        bput(Da.x, Sa.x);
        bput(Da.y, Sa.y);
        bput(Da.z, Sa.z);
        bput(Da.w, Sa.w);
        bput(Db.x, Sb.x);
        bput(Db.y, Sb.y);
        bput(Db.z, Sb.z);
        bput(Db.w, Sb.w);
    } else if (t < SCAT_T) {
        int m = t - NE8;
        int n0 = m * 4;
        const float4* xv = reinterpret_cast<const float4*>(x) + m * 3;
        float4 a = __ldg(xv), b = __ldg(xv + 1), c = __ldg(xv + 2);
        g_x4[n0 + 0] = make_float4(a.x, a.y, a.z, 0.f);
        g_x4[n0 + 1] = make_float4(a.w, b.x, b.y, 0.f);
        g_x4[n0 + 2] = make_float4(b.z, b.w, c.x, 0.f);
        g_x4[n0 + 3] = make_float4(c.y, c.z, c.w, 0.f);
        bput(n0 + 0, n0 + 0);
        bput(n0 + 1, n0 + 1);
        bput(n0 + 2, n0 + 2);
        bput(n0 + 3, n0 + 3);
    }
}

// ---------------- layer 1: fused gather-softmax-agg-transform + ELU ----------
// 512 threads = 16 warps = 16 nodes/block; PDL: smem fill overlaps k_scatter.
__global__ __launch_bounds__(512)
void k_l1_agg(const float* __restrict__ W1,
              const float* __restrict__ bias1) {
    __shared__ float W1s[PAD(767) + 1];   // padded, conflict-free for stride-8
    __shared__ float b1s[PAD(255) + 1];
    for (int i = threadIdx.x; i < 768; i += 512) W1s[PAD(i)] = W1[i];
    if (threadIdx.x < 256) b1s[PAD(threadIdx.x)] = bias1[threadIdx.x];
    cudaGridDependencySynchronize();      // wait for k_scatter results
    __syncthreads();

    int n = blockIdx.x * 16 + (threadIdx.x >> 5);   // 3125*16 = 50000 exact
    int lane = threadIdx.x & 31;
    int deg  = min(g_cursor[n], CAP);
    const unsigned short* row = g_bkt + n * CAP;

    int q = lane & 3;     // heads q and q+4
    int g = lane >> 2;    // edge subgroup 0..7

    float A00 = g_As1[q],     A01 = g_As1[8 + q],  A02 = g_As1[16 + q];
    float A10 = g_As1[4 + q], A11 = g_As1[12 + q], A12 = g_As1[20 + q];
    float4 xn = g_x4[n];
    float adh0 = fmaf(xn.x, g_Ad1[q],     fmaf(xn.y, g_Ad1[8 + q],  xn.z * g_Ad1[16 + q]));
    float adh1 = fmaf(xn.x, g_Ad1[4 + q], fmaf(xn.y, g_Ad1[12 + q], xn.z * g_Ad1[20 + q]));

    float sx0 = 0.f, sy0 = 0.f, sz0 = 0.f, sw0 = 0.f;
    float sx1 = 0.f, sy1 = 0.f, sz1 = 0.f, sw1 = 0.f;

    for (int j = g; j < deg; j += 8) {
        int s = (int)row[j];                 // 4 lanes same addr -> broadcast
        float4 xs = __ldg(&g_x4[s]);         // one LDG.128 per subgroup
        float as0 = fmaf(xs.x, A00, fmaf(xs.y, A01, xs.z * A02));
        float as1 = fmaf(xs.x, A10, fmaf(xs.y, A11, xs.z * A12));
        float w0 = __expf(lrelu(as0 + adh0));
        float w1 = __expf(lrelu(as1 + adh1));
        sw0 += w0;
        sx0 = fmaf(w0, xs.x, sx0); sy0 = fmaf(w0, xs.y, sy0); sz0 = fmaf(w0, xs.z, sz0);
        sw1 += w1;
        sx1 = fmaf(w1, xs.x, sx1); sy1 = fmaf(w1, xs.y, sy1); sz1 = fmaf(w1, xs.z, sz1);
    }
    #pragma unroll
    for (int off = 4; off <= 16; off <<= 1) {
        sx0 += __shfl_xor_sync(FULL, sx0, off);
        sy0 += __shfl_xor_sync(FULL, sy0, off);
        sz0 += __shfl_xor_sync(FULL, sz0, off);
        sw0 += __shfl_xor_sync(FULL, sw0, off);
        sx1 += __shfl_xor_sync(FULL, sx1, off);
        sy1 += __shfl_xor_sync(FULL, sy1, off);
        sz1 += __shfl_xor_sync(FULL, sz1, off);
        sw1 += __shfl_xor_sync(FULL, sw1, off);
    }

    // epilogue: lane covers channels [lane*8, lane*8+8), head hc = lane>>2
    int hc = lane >> 2;
    int srcl = hc & 3;
    float tx0 = __shfl_sync(FULL, sx0, srcl), tx1 = __shfl_sync(FULL, sx1, srcl);
    float ty0 = __shfl_sync(FULL, sy0, srcl), ty1 = __shfl_sync(FULL, sy1, srcl);
    float tz0 = __shfl_sync(FULL, sz0, srcl), tz1 = __shfl_sync(FULL, sz1, srcl);
    float tw0 = __shfl_sync(FULL, sw0, srcl), tw1 = __shfl_sync(FULL, sw1, srcl);
    bool lo = hc < 4;
    float ex = lo ? tx0 : tx1;
    float ey = lo ? ty0 : ty1;
    float ez = lo ? tz0 : tz1;
    float ew = lo ? tw0 : tw1;
    float inv = 1.0f / (ew + 1e-16f);
    ex *= inv; ey *= inv; ez *= inv;

    int c0 = lane * 8;
    float o[8];
    #pragma unroll
    for (int i = 0; i < 8; i++) {
        int k = c0 + i;
        float v = fmaf(ex, W1s[PAD(k)],
                  fmaf(ey, W1s[PAD(256 + k)], ez * W1s[PAD(512 + k)]));
        v += b1s[PAD(k)];
        o[i] = v > 0.f ? v : (__expf(v) - 1.0f);
    }
    __half2 p0 = __floats2half2_rn(o[0], o[1]);
    __half2 p1 = __floats2half2_rn(o[2], o[3]);
    __half2 p2 = __floats2half2_rn(o[4], o[5]);
    __half2 p3 = __floats2half2_rn(o[6], o[7]);
    uint4 pack;
    pack.x = *reinterpret_cast<unsigned int*>(&p0);
    pack.y = *reinterpret_cast<unsigned int*>(&p1);
    pack.z = *reinterpret_cast<unsigned int*>(&p2);
    pack.w = *reinterpret_cast<unsigned int*>(&p3);
    reinterpret_cast<uint4*>(g_hmid_h)[n * 32 + lane] = pack;
}

// ---------------- layer 2: node transform (256 -> 16), fp16 in/out -----------
// 1024 threads = 64 nodes/block; PDL: W2 smem fill overlaps k_l1_agg.
__global__ __launch_bounds__(1024)
void k_l2_node(const float* __restrict__ W2,
               const float* __restrict__ att_s,
               const float* __restrict__ att_d) {
    __shared__ float W2s[D1 * D2];   // 16 KB
    for (int i = threadIdx.x; i < D1 * D2; i += 1024) W2s[i] = W2[i];
    cudaGridDependencySynchronize();      // wait for hmid
    __syncthreads();

    int grp = threadIdx.x >> 4;
    int c   = threadIdx.x & 15;
    int n = blockIdx.x * 64 + grp;
    if (n >= NN) return;

    const uint4* row = reinterpret_cast<const uint4*>(g_hmid_h + n * D1);
    float acc = 0.f;
    #pragma unroll 8
    for (int q = 0; q < 32; q++) {
        uint4 v = row[q];
        int k = q * 8;
        const __half2* p = reinterpret_cast<const __half2*>(&v);
        #pragma unroll
        for (int t = 0; t < 4; t++) {
            float2 f = __half22float2(p[t]);
            acc = fmaf(f.x, W2s[(k + 2 * t) * D2 + c], acc);
            acc = fmaf(f.y, W2s[(k + 2 * t + 1) * D2 + c], acc);
        }
    }
    g_h2h[n * D2 + c] = __float2half_rn(acc);
    float sa = acc * att_s[c];
    float sd = acc * att_d[c];
    #pragma unroll
    for (int off = 8; off > 0; off >>= 1) {
        sa += __shfl_xor_sync(FULL, sa, off);
        sd += __shfl_xor_sync(FULL, sd, off);
    }
    if (c == 0) { g_as2[n] = sa; g_ad2[n] = sd; }
}

// ---------------- layer 2: single-pass softmax-agg ---------------------------
// one warp per dst node; 8 edge subgroups x 4 lanes, each lane owns 4 channels.
__global__ void k_l2_agg(const float* __restrict__ bias2,
                         float* __restrict__ out) {
    cudaGridDependencySynchronize();      // wait for h2/as2/ad2
    int n = blockIdx.x * 8 + (threadIdx.x >> 5);
    if (n >= NN) return;
    int lane = threadIdx.x & 31;
    int deg  = min(g_cursor[n], CAP);
    const unsigned short* row = g_bkt + n * CAP;
    float adn = g_ad2[n];

    int q = lane & 3;         // channel quad owner: channels 4q..4q+3
    int g = lane >> 2;        // edge subgroup 0..7

    float a0 = 0.f, a1 = 0.f, a2 = 0.f, a3 = 0.f, wsum = 0.f;
    for (int j = g; j < deg; j += 8) {
        int s = (int)row[j];                           // broadcast in subgroup
        float w = __expf(lrelu(g_as2[s] + adn));       // broadcast load
        uint2 v = *reinterpret_cast<const uint2*>(g_h2h + s * D2 + q * 4);
        float2 f0 = __half22float2(*reinterpret_cast<__half2*>(&v.x));
        float2 f1 = __half22float2(*reinterpret_cast<__half2*>(&v.y));
        a0 = fmaf(w, f0.x, a0);
        a1 = fmaf(w, f0.y, a1);
        a2 = fmaf(w, f1.x, a2);
        a3 = fmaf(w, f1.y, a3);
        wsum += w;
    }
    #pragma unroll
    for (int off = 4; off <= 16; off <<= 1) {
        a0   += __shfl_xor_sync(FULL, a0, off);
        a1   += __shfl_xor_sync(FULL, a1, off);
        a2   += __shfl_xor_sync(FULL, a2, off);
        a3   += __shfl_xor_sync(FULL, a3, off);
        wsum += __shfl_xor_sync(FULL, wsum, off);
    }
    if (lane < 4) {
        float inv = 1.0f / (wsum + 1e-16f);
        int c = q * 4;
        float4 r;
        r.x = a0 * inv + bias2[c];
        r.y = a1 * inv + bias2[c + 1];
        r.z = a2 * inv + bias2[c + 2];
        r.w = a3 * inv + bias2[c + 3];
        *reinterpret_cast<float4*>(out + n * D2 + c) = r;
    }
    if (lane == 0) g_cursor[n] = 0;   // restore zero invariant
}

// ---------------- launch (PDL-chained) ----------------------------------------
template <typename K, typename... Args>
static void launch_pdl(K kernel, dim3 grid, dim3 block, Args... args) {
    cudaLaunchConfig_t cfg = {};
    cfg.gridDim = grid;
    cfg.blockDim = block;
    cfg.stream = 0;
    cudaLaunchAttribute attr[1];
    attr[0].id = cudaLaunchAttributeProgrammaticStreamSerialization;
    attr[0].val.programmaticStreamSerializationAllowed = 1;
    cfg.attrs = attr;
    cfg.numAttrs = 1;
    cudaLaunchKernelEx(&cfg, kernel, args...);
}

extern "C" void kernel_launch(void* const* d_in, const int* in_sizes, int n_in,
                              void* d_out, int out_size) {
    const float* x      = (const float*)d_in[0];
    const int*   ei     = (const int*)d_in[1];   // JAX x64 disabled -> int32
    const float* W1     = (const float*)d_in[2];
    const float* atts1  = (const float*)d_in[3];
    const float* attd1  = (const float*)d_in[4];
    const float* bias1  = (const float*)d_in[5];
    const float* W2     = (const float*)d_in[6];
    const float* atts2  = (const float*)d_in[7];
    const float* attd2  = (const float*)d_in[8];
    const float* bias2  = (const float*)d_in[9];
    float* out = (float*)d_out;

    int sb = (SCAT_T + 255) / 256;
    k_scatter<<<sb + 1, 256>>>(ei, x, W1, atts1, attd1);   // +1 block does prep
    launch_pdl(k_l1_agg, dim3(NN / 16), dim3(512), W1, bias1);
    launch_pdl(k_l2_node, dim3((NN + 63) / 64), dim3(1024), W2, atts2, attd2);
    launch_pdl(k_l2_agg, dim3((NN + 7) / 8), dim3(256), bias2, out);
}